// round 7
// baseline (speedup 1.0000x reference)
#include <cuda_runtime.h>
#include <cuda_fp16.h>
#include <cstdint>

#define N_ROWS   32768
#define D_DIM    256
#define K_CODES  1024
#define OUT_ELEMS 8388608
#define MARGIN   4e-3f

// ---------------- device scratch ----------------
__device__ float  g_wsq[K_CODES];
__device__ float  g_wT[K_CODES * D_DIM];            // exact fp32 transpose
__device__ __align__(16) __half g_wBpk[8][8][4096]; // fp16 prepacked B image [ct128][ch]
__device__ float  g_partial[512];

// ---------------- fused kernel SMEM layout (bytes) ----------------
#define SCR_OFF   0          // 64 x 1032 halves = 132096 (also z fp32 staging, later qtile)
#define SCR_PH    1032       // halves per scr row (pitch)
#define A_OFF     132096     // 2048 uint4 = 32768
#define B_OFF     164864     // 2 stages x 16384
#define SUMZ_OFF  197632     // 64 floats
#define SMIN_OFF  197888     // 64 x 8 floats
#define THR_OFF   199936     // 64 floats
#define CLO_OFF   200192     // 64 ints
#define RED_OFF   200448     // 256 floats
#define FUSED_SMEM 201472
#define ZP 264               // z staging pitch (floats)
#define QP 257               // qtile pitch (floats)

// ---------------- helpers ----------------
__device__ __forceinline__ uint32_t smem_u32(const void* p) {
    uint32_t a;
    asm("{ .reg .u64 t; cvta.to.shared.u64 t, %1; cvt.u32.u64 %0, t; }" : "=r"(a) : "l"(p));
    return a;
}
__device__ __forceinline__ uint32_t f2h2(float a, float b) {
    __half2 h = __floats2half2_rn(a, b);
    return *reinterpret_cast<uint32_t*>(&h);
}
__device__ __forceinline__ void cpasync16(uint32_t dst, const void* src) {
    asm volatile("cp.async.cg.shared.global [%0], [%1], 16;" :: "r"(dst), "l"(src));
}
__device__ __forceinline__ void mma_f16(float* c, uint32_t a0, uint32_t a1, uint32_t a2, uint32_t a3,
                                        uint32_t b0, uint32_t b1) {
    asm volatile(
        "mma.sync.aligned.m16n8k16.row.col.f32.f16.f16.f32 "
        "{%0,%1,%2,%3}, {%4,%5,%6,%7}, {%8,%9}, {%0,%1,%2,%3};"
        : "+f"(c[0]), "+f"(c[1]), "+f"(c[2]), "+f"(c[3])
        : "r"(a0), "r"(a1), "r"(a2), "r"(a3), "r"(b0), "r"(b1));
}

// ---------------- kernel 1: wsq ----------------
__global__ void wsq_kernel(const float* __restrict__ w) {
    int k = blockIdx.x * 256 + threadIdx.x;
    float s = 0.f;
    #pragma unroll 8
    for (int d = 0; d < D_DIM; d++) {
        float v = w[d * K_CODES + k];
        s = fmaf(v, v, s);
    }
    g_wsq[k] = s;
}

// ---------------- kernel 2: transpose + fp16 prepack of w ----------------
__global__ void splitw_kernel(const float* __restrict__ w) {
    __shared__ float t[32][33];
    int k0 = blockIdx.x * 32, d0 = blockIdx.y * 32;   // grid (32, 8), block (32, 8)
    int x = threadIdx.x, y = threadIdx.y;
    #pragma unroll
    for (int i = 0; i < 32; i += 8)
        t[y + i][x] = w[(d0 + y + i) * K_CODES + k0 + x];
    __syncthreads();
    #pragma unroll
    for (int i = 0; i < 32; i += 8) {
        float v = t[x][y + i];
        int code = k0 + y + i, d = d0 + x;
        g_wT[code * D_DIM + d] = v;
        int ct = code >> 7, n = code & 127, ch = d >> 5, kw = d & 31;
        int kg = kw >> 4, ko = kw & 15;
        int tig = (ko & 7) >> 1, pp = ko & 1, hi = (ko >> 3) & 1;
        int gg = n & 7, nb = n >> 3;
        int u2idx = (kg * 16 + nb) * 32 + gg * 4 + tig;
        g_wBpk[ct][ch][u2idx * 4 + hi * 2 + pp] = __float2half(v);
    }
}

// ---------------- kernel 3: fused screen + select + rescore + output ----------------
// grid 512, block 256 (8 warps). Block: rows n0..n0+64, all 1024 codes.
__global__ void __launch_bounds__(256) fused_kernel(const float* __restrict__ z,
                                                    float* __restrict__ out) {
    extern __shared__ char sm[];
    const uint32_t sb = smem_u32(sm);
    const int tid = threadIdx.x, wid = tid >> 5, lane = tid & 31;
    const int g = lane >> 2, tig = lane & 3;
    const int n0 = blockIdx.x * 64;

    float*   zst   = reinterpret_cast<float*>(sm + SCR_OFF);
    float*   sumzA = reinterpret_cast<float*>(sm + SUMZ_OFF);
    float*   sminA = reinterpret_cast<float*>(sm + SMIN_OFF);
    float*   thrA  = reinterpret_cast<float*>(sm + THR_OFF);
    int*     cloA  = reinterpret_cast<int*>(sm + CLO_OFF);
    float*   redA  = reinterpret_cast<float*>(sm + RED_OFF);
    __half2* scrH  = reinterpret_cast<__half2*>(sm + SCR_OFF);

    sminA[tid] = 1e30f;
    sminA[tid + 256] = 1e30f;

    // ---- phase 1: stage z (fp32) into SMEM ----
    #pragma unroll
    for (int i = 0; i < 16; i++) {
        int idx = i * 256 + tid;               // float4 index
        int row = idx >> 6, c4 = idx & 63;
        float4 v = *reinterpret_cast<const float4*>(z + (size_t)(n0 + row) * D_DIM + c4 * 4);
        *reinterpret_cast<float4*>(zst + row * ZP + c4 * 4) = v;
    }
    __syncthreads();

    // ---- phase 1b: sumz (warp w -> rows w*8..+7) ----
    #pragma unroll
    for (int i = 0; i < 8; i++) {
        int r = wid * 8 + i;
        float s = 0.f;
        #pragma unroll
        for (int j = 0; j < 8; j++) {
            float v = zst[r * ZP + lane + 32 * j];
            s = fmaf(v, v, s);
        }
        #pragma unroll
        for (int o = 16; o > 0; o >>= 1) s += __shfl_down_sync(0xffffffffu, s, o);
        if (lane == 0) sumzA[r] = s;
    }

    // ---- phase 1c: build A fragment image (all 256 k) ----
    {
        const int b = tid >> 6, gg = (tid >> 3) & 7, kg = (tid >> 2) & 1, tg = tid & 3;
        const int r0 = b * 16 + gg, r1 = r0 + 8;
        uint4* A4 = reinterpret_cast<uint4*>(sm + A_OFF);
        #pragma unroll
        for (int ch = 0; ch < 8; ch++) {
            int kb = ch * 32 + kg * 16 + 2 * tg;
            float2 p0 = *reinterpret_cast<float2*>(zst + r0 * ZP + kb);
            float2 p1 = *reinterpret_cast<float2*>(zst + r1 * ZP + kb);
            float2 p2 = *reinterpret_cast<float2*>(zst + r0 * ZP + kb + 8);
            float2 p3 = *reinterpret_cast<float2*>(zst + r1 * ZP + kb + 8);
            uint4 u;
            u.x = f2h2(p0.x, p0.y);
            u.y = f2h2(p1.x, p1.y);
            u.z = f2h2(p2.x, p2.y);
            u.w = f2h2(p3.x, p3.y);
            A4[((b * 8 + ch) * 2 + kg) * 32 + gg * 4 + tg] = u;
        }
    }

    // B chunk fill: (ctp group of 256 codes, ch) -> stage st, 16KB
    auto fillB = [&](int cc2) {
        int ctp2 = cc2 >> 3, ch2 = cc2 & 7, st = cc2 & 1;
        uint32_t dst = sb + B_OFF + st * 16384;
        #pragma unroll
        for (int q = 0; q < 4; q++) {
            int idx = tid + q * 256;
            int im = idx >> 9, off = idx & 511;
            cpasync16(dst + im * 8192 + off * 16,
                      reinterpret_cast<const char*>(&g_wBpk[ctp2 * 2 + im][ch2][0]) + off * 16);
        }
        asm volatile("cp.async.commit_group;");
    };

    fillB(0);
    fillB(1);
    __syncthreads();   // phase-1 consumption of zst complete; A image visible

    // ---- phase 2: main GEMM loop, 32 chunks (4 ct groups x 8 k-chunks) ----
    const int image = wid >> 2, slab = wid & 3;
    float C[4][4][4];

    for (int cc = 0; cc < 32; cc++) {
        const int s = cc & 1, ctp = cc >> 3, ch = cc & 7;
        if (cc == 31) { asm volatile("cp.async.wait_group 0;" ::: "memory"); }
        else         { asm volatile("cp.async.wait_group 1;" ::: "memory"); }
        __syncthreads();

        if (ch == 0) {
            #pragma unroll
            for (int m = 0; m < 4; m++)
                #pragma unroll
                for (int j = 0; j < 4; j++)
                    #pragma unroll
                    for (int q = 0; q < 4; q++) C[m][j][q] = 0.f;
        }

        const uint4* A4 = reinterpret_cast<const uint4*>(sm + A_OFF);
        const uint2* B2 = reinterpret_cast<const uint2*>(sm + B_OFF + s * 16384 + image * 8192);
        #pragma unroll
        for (int kg = 0; kg < 2; kg++) {
            uint2 bf[4];
            #pragma unroll
            for (int j = 0; j < 4; j++)
                bf[j] = B2[(kg * 16 + slab * 4 + j) * 32 + lane];
            #pragma unroll
            for (int m = 0; m < 4; m++) {
                uint4 a = A4[((m * 8 + ch) * 2 + kg) * 32 + lane];
                #pragma unroll
                for (int j = 0; j < 4; j++)
                    mma_f16(C[m][j], a.x, a.y, a.z, a.w, bf[j].x, bf[j].y);
            }
        }

        if (ch == 7) {
            // epilogue for ct group: c = wsq - 2*dot -> scr fp16; per-row running min
            #pragma unroll
            for (int m = 0; m < 4; m++) {
                int r = m * 16 + g;
                float mn0 = 1e30f, mn1 = 1e30f;
                #pragma unroll
                for (int j = 0; j < 4; j++) {
                    int col = ctp * 256 + image * 128 + slab * 32 + j * 8 + 2 * tig;
                    float w0 = g_wsq[col], w1 = g_wsq[col + 1];
                    float s00 = fmaf(-2.f, C[m][j][0], w0);
                    float s01 = fmaf(-2.f, C[m][j][1], w1);
                    float s10 = fmaf(-2.f, C[m][j][2], w0);
                    float s11 = fmaf(-2.f, C[m][j][3], w1);
                    scrH[r * (SCR_PH / 2) + (col >> 1)]       = __floats2half2_rn(s00, s01);
                    scrH[(r + 8) * (SCR_PH / 2) + (col >> 1)] = __floats2half2_rn(s10, s11);
                    mn0 = fminf(mn0, fminf(s00, s01));
                    mn1 = fminf(mn1, fminf(s10, s11));
                }
                #pragma unroll
                for (int o = 1; o < 4; o <<= 1) {
                    mn0 = fminf(mn0, __shfl_xor_sync(0xffffffffu, mn0, o));
                    mn1 = fminf(mn1, __shfl_xor_sync(0xffffffffu, mn1, o));
                }
                if (tig == 0) {
                    sminA[r * 8 + wid] = fminf(sminA[r * 8 + wid], mn0);
                    sminA[(r + 8) * 8 + wid] = fminf(sminA[(r + 8) * 8 + wid], mn1);
                }
            }
        }
        __syncthreads();
        if (cc + 2 < 32) fillB(cc + 2);
    }

    // ---- phase 3: per-row thresholds ----
    if (tid < 64) {
        float v = sminA[tid * 8];
        #pragma unroll
        for (int t = 1; t < 8; t++) v = fminf(v, sminA[tid * 8 + t]);
        thrA[tid] = v + MARGIN;
    }
    __syncthreads();

    // ---- phase 4: candidate scan (SMEM) + exact fp32 rescore ----
    for (int i = 0; i < 8; i++) {
        int r = wid * 8 + i;
        float thr_r = thrA[r], sz = sumzA[r];
        float zr[8];
        #pragma unroll
        for (int j = 0; j < 8; j++)
            zr[j] = z[(size_t)(n0 + r) * D_DIM + lane + 32 * j];
        float best = 1e30f; int besti = 0;
        for (int ccb = 0; ccb < 16; ccb++) {
            __half2 h = scrH[r * (SCR_PH / 2) + ccb * 32 + lane];
            unsigned m2 = (__low2float(h) <= thr_r ? 1u : 0u) |
                          (__high2float(h) <= thr_r ? 2u : 0u);
            unsigned bal = __ballot_sync(0xffffffffu, m2 != 0);
            while (bal) {
                int src = __ffs(bal) - 1;
                bal &= bal - 1;
                unsigned mm = __shfl_sync(0xffffffffu, m2, src);
                #pragma unroll
                for (int bit = 0; bit < 2; bit++) {
                    if ((mm >> bit) & 1) {
                        int k = (ccb * 32 + src) * 2 + bit;     // ascending k order
                        const float* wr = g_wT + (size_t)k * D_DIM;
                        float acc = 0.f;
                        #pragma unroll
                        for (int j = 0; j < 8; j++)
                            acc = fmaf(zr[j], wr[lane + 32 * j], acc);
                        #pragma unroll
                        for (int o = 16; o > 0; o >>= 1)
                            acc += __shfl_down_sync(0xffffffffu, acc, o);
                        if (lane == 0) {
                            float t = sz + g_wsq[k];
                            float dist = fmaf(-2.f, acc, t);
                            if (dist < best) { best = dist; besti = k; }
                        }
                    }
                }
            }
        }
        if (lane == 0) cloA[r] = besti;
    }
    __syncthreads();

    // ---- phase 5a: gather + loss partial + stage output tile (reuses scr region) ----
    float part = 0.f;
    float* qt = reinterpret_cast<float*>(sm + SCR_OFF);
    for (int i = 0; i < 8; i++) {
        int r = wid * 8 + i;
        int k = cloA[r];
        const float* wr = g_wT + (size_t)k * D_DIM;
        const float* zrow = z + (size_t)(n0 + r) * D_DIM;
        #pragma unroll
        for (int j = 0; j < 8; j++) {
            int d = lane + 32 * j;
            float q = wr[d], zv = zrow[d];
            float df = q - zv;
            part = fmaf(df, df, part);
            qt[r * QP + d] = zv + df;     // fl(z + fl(q - z)) matches ref ST
        }
    }

    redA[tid] = part;
    __syncthreads();
    #pragma unroll
    for (int st = 128; st > 0; st >>= 1) {
        if (tid < st) redA[tid] += redA[tid + st];
        __syncthreads();
    }
    if (tid == 0) g_partial[blockIdx.x] = redA[0];

    // ---- phase 5b: transposed write-out [B, D, H, W] (FIXED: full 64x256 tile) ----
    // Each thread writes a float4 along hw: 16 iters x 256 thr x 4 = 16384 elements.
    int b = n0 >> 10, hw0 = n0 & 1023;
    #pragma unroll
    for (int i = 0; i < 16; i++) {
        int lin = i * 256 + tid;
        int d = lin >> 4;                // 0..255
        int hw4 = (lin & 15) * 4;        // 0,4,...,60
        float4 v;
        v.x = qt[(hw4 + 0) * QP + d];
        v.y = qt[(hw4 + 1) * QP + d];
        v.z = qt[(hw4 + 2) * QP + d];
        v.w = qt[(hw4 + 3) * QP + d];
        *reinterpret_cast<float4*>(out + (size_t)b * 262144 + (size_t)d * 1024 + hw0 + hw4) = v;
    }
}

// ---------------- kernel 4: finalize losses ----------------
__global__ void finalize_kernel(float* __restrict__ out, int out_size) {
    __shared__ double sdata[256];
    int tid = threadIdx.x;
    double s = (double)g_partial[tid] + (double)g_partial[tid + 256];
    sdata[tid] = s;
    __syncthreads();
    #pragma unroll
    for (int st = 128; st > 0; st >>= 1) {
        if (tid < st) sdata[tid] += sdata[tid + st];
        __syncthreads();
    }
    if (tid == 0) {
        float loss = (float)(sdata[0] / (double)OUT_ELEMS);
        out[out_size - 2] = loss;
        out[out_size - 1] = loss;
    }
}

// ---------------- launcher ----------------
extern "C" void kernel_launch(void* const* d_in, const int* in_sizes, int n_in,
                              void* d_out, int out_size) {
    (void)in_sizes; (void)n_in;
    const float* z = (const float*)d_in[0];
    const float* w = (const float*)d_in[1];
    float* out = (float*)d_out;

    static int inited = 0;
    if (!inited) {
        cudaFuncSetAttribute(fused_kernel, cudaFuncAttributeMaxDynamicSharedMemorySize, FUSED_SMEM);
        inited = 1;
    }

    wsq_kernel<<<K_CODES / 256, 256>>>(w);
    splitw_kernel<<<dim3(K_CODES / 32, D_DIM / 32), dim3(32, 8)>>>(w);
    fused_kernel<<<N_ROWS / 64, 256, FUSED_SMEM>>>(z, out);
    finalize_kernel<<<1, 256>>>(out, out_size);
}

// round 8
// speedup vs baseline: 1.2552x; 1.2552x over previous
#include <cuda_runtime.h>
#include <cuda_fp16.h>
#include <cstdint>

#define N_ROWS   32768
#define D_DIM    256
#define K_CODES  1024
#define OUT_ELEMS 8388608
#define MARGIN   4e-3f
#define CAND_MAX 64

// ---------------- device scratch ----------------
__device__ float  g_wsq[K_CODES];
__device__ float  g_wT[K_CODES * D_DIM];            // exact fp32 transpose
__device__ __align__(16) __half g_wBpk[8][8][4096]; // fp16 prepacked B image [ct128][ch]
__device__ float  g_partial[512];

// ---------------- fused kernel SMEM layout (bytes) ----------------
// A image:      [0, 32768)
// overlay X:    [32768, 100352)  phase1: zst 64xZP fp32 (67584)
//                                phase2: B 2x16384 @32768, cand 64x64 int @65536
//                                phase5: qtile 64xQP fp32 (65792) @32768
// misc:         [100352, 104448)
#define A_OFF     0
#define X_OFF     32768
#define B_OFF     32768
#define CAND_OFF  65536
#define SUMZ_OFF  100352
#define SMIN_OFF  100608
#define THR_OFF   102656
#define CNT_OFF   102912
#define CLO_OFF   103168
#define RED_OFF   103424
#define FUSED_SMEM 104448
#define ZP 264
#define QP 257

// ---------------- helpers ----------------
__device__ __forceinline__ uint32_t smem_u32(const void* p) {
    uint32_t a;
    asm("{ .reg .u64 t; cvta.to.shared.u64 t, %1; cvt.u32.u64 %0, t; }" : "=r"(a) : "l"(p));
    return a;
}
__device__ __forceinline__ uint32_t f2h2(float a, float b) {
    __half2 h = __floats2half2_rn(a, b);
    return *reinterpret_cast<uint32_t*>(&h);
}
__device__ __forceinline__ void cpasync16(uint32_t dst, const void* src) {
    asm volatile("cp.async.cg.shared.global [%0], [%1], 16;" :: "r"(dst), "l"(src));
}
__device__ __forceinline__ void mma_f16(float* c, uint32_t a0, uint32_t a1, uint32_t a2, uint32_t a3,
                                        uint32_t b0, uint32_t b1) {
    asm volatile(
        "mma.sync.aligned.m16n8k16.row.col.f32.f16.f16.f32 "
        "{%0,%1,%2,%3}, {%4,%5,%6,%7}, {%8,%9}, {%0,%1,%2,%3};"
        : "+f"(c[0]), "+f"(c[1]), "+f"(c[2]), "+f"(c[3])
        : "r"(a0), "r"(a1), "r"(a2), "r"(a3), "r"(b0), "r"(b1));
}

// ---------------- kernel 1: wsq ----------------
__global__ void wsq_kernel(const float* __restrict__ w) {
    int k = blockIdx.x * 256 + threadIdx.x;
    float s = 0.f;
    #pragma unroll 8
    for (int d = 0; d < D_DIM; d++) {
        float v = w[d * K_CODES + k];
        s = fmaf(v, v, s);
    }
    g_wsq[k] = s;
}

// ---------------- kernel 2: transpose + fp16 prepack of w ----------------
__global__ void splitw_kernel(const float* __restrict__ w) {
    __shared__ float t[32][33];
    int k0 = blockIdx.x * 32, d0 = blockIdx.y * 32;   // grid (32, 8), block (32, 8)
    int x = threadIdx.x, y = threadIdx.y;
    #pragma unroll
    for (int i = 0; i < 32; i += 8)
        t[y + i][x] = w[(d0 + y + i) * K_CODES + k0 + x];
    __syncthreads();
    #pragma unroll
    for (int i = 0; i < 32; i += 8) {
        float v = t[x][y + i];
        int code = k0 + y + i, d = d0 + x;
        g_wT[code * D_DIM + d] = v;
        int ct = code >> 7, n = code & 127, ch = d >> 5, kw = d & 31;
        int kg = kw >> 4, ko = kw & 15;
        int tig = (ko & 7) >> 1, pp = ko & 1, hi = (ko >> 3) & 1;
        int gg = n & 7, nb = n >> 3;
        int u2idx = (kg * 16 + nb) * 32 + gg * 4 + tig;
        g_wBpk[ct][ch][u2idx * 4 + hi * 2 + pp] = __float2half(v);
    }
}

// ---------------- kernel 3: fused screen + candidate select + rescore + output ----------------
// grid 512, block 256 (8 warps). Block: rows n0..n0+64, all 1024 codes.
__global__ void __launch_bounds__(256, 2) fused_kernel(const float* __restrict__ z,
                                                       float* __restrict__ out) {
    extern __shared__ char sm[];
    const uint32_t sb = smem_u32(sm);
    const int tid = threadIdx.x, wid = tid >> 5, lane = tid & 31;
    const int g = lane >> 2, tig = lane & 3;
    const int n0 = blockIdx.x * 64;

    float* zst   = reinterpret_cast<float*>(sm + X_OFF);
    int*   candA = reinterpret_cast<int*>(sm + CAND_OFF);
    float* sumzA = reinterpret_cast<float*>(sm + SUMZ_OFF);
    float* sminA = reinterpret_cast<float*>(sm + SMIN_OFF);
    float* thrA  = reinterpret_cast<float*>(sm + THR_OFF);
    int*   cntA  = reinterpret_cast<int*>(sm + CNT_OFF);
    int*   cloA  = reinterpret_cast<int*>(sm + CLO_OFF);
    float* redA  = reinterpret_cast<float*>(sm + RED_OFF);

    sminA[tid] = 1e30f;
    sminA[tid + 256] = 1e30f;
    if (tid < 64) cntA[tid] = 0;

    // ---- phase 1: stage z (fp32) into SMEM ----
    #pragma unroll
    for (int i = 0; i < 16; i++) {
        int idx = i * 256 + tid;
        int row = idx >> 6, c4 = idx & 63;
        float4 v = *reinterpret_cast<const float4*>(z + (size_t)(n0 + row) * D_DIM + c4 * 4);
        *reinterpret_cast<float4*>(zst + row * ZP + c4 * 4) = v;
    }
    __syncthreads();

    // ---- phase 1b: sumz ----
    #pragma unroll
    for (int i = 0; i < 8; i++) {
        int r = wid * 8 + i;
        float s = 0.f;
        #pragma unroll
        for (int j = 0; j < 8; j++) {
            float v = zst[r * ZP + lane + 32 * j];
            s = fmaf(v, v, s);
        }
        #pragma unroll
        for (int o = 16; o > 0; o >>= 1) s += __shfl_down_sync(0xffffffffu, s, o);
        if (lane == 0) sumzA[r] = s;
    }

    // ---- phase 1c: build A fragment image (all 256 k) ----
    {
        const int b = tid >> 6, gg = (tid >> 3) & 7, kg = (tid >> 2) & 1, tg = tid & 3;
        const int r0 = b * 16 + gg, r1 = r0 + 8;
        uint4* A4 = reinterpret_cast<uint4*>(sm + A_OFF);
        #pragma unroll
        for (int ch = 0; ch < 8; ch++) {
            int kb = ch * 32 + kg * 16 + 2 * tg;
            float2 p0 = *reinterpret_cast<float2*>(zst + r0 * ZP + kb);
            float2 p1 = *reinterpret_cast<float2*>(zst + r1 * ZP + kb);
            float2 p2 = *reinterpret_cast<float2*>(zst + r0 * ZP + kb + 8);
            float2 p3 = *reinterpret_cast<float2*>(zst + r1 * ZP + kb + 8);
            uint4 u;
            u.x = f2h2(p0.x, p0.y);
            u.y = f2h2(p1.x, p1.y);
            u.z = f2h2(p2.x, p2.y);
            u.w = f2h2(p3.x, p3.y);
            A4[((b * 8 + ch) * 2 + kg) * 32 + gg * 4 + tg] = u;
        }
    }
    __syncthreads();   // zst fully consumed; B overlay may now be written

    // B chunk fill
    auto fillB = [&](int cc2) {
        int ctp2 = cc2 >> 3, ch2 = cc2 & 7, st = cc2 & 1;
        uint32_t dst = sb + B_OFF + st * 16384;
        #pragma unroll
        for (int q = 0; q < 4; q++) {
            int idx = tid + q * 256;
            int im = idx >> 9, off = idx & 511;
            cpasync16(dst + im * 8192 + off * 16,
                      reinterpret_cast<const char*>(&g_wBpk[ctp2 * 2 + im][ch2][0]) + off * 16);
        }
        asm volatile("cp.async.commit_group;");
    };

    fillB(0);
    fillB(1);

    // ---- phase 2: main GEMM loop ----
    const int image = wid >> 2, slab = wid & 3;
    float C[4][4][4];

    for (int cc = 0; cc < 32; cc++) {
        const int s = cc & 1, ctp = cc >> 3, ch = cc & 7;
        if (cc == 31) { asm volatile("cp.async.wait_group 0;" ::: "memory"); }
        else         { asm volatile("cp.async.wait_group 1;" ::: "memory"); }
        __syncthreads();

        if (ch == 0) {
            #pragma unroll
            for (int m = 0; m < 4; m++)
                #pragma unroll
                for (int j = 0; j < 4; j++)
                    #pragma unroll
                    for (int q = 0; q < 4; q++) C[m][j][q] = 0.f;
        }

        const uint4* A4 = reinterpret_cast<const uint4*>(sm + A_OFF);
        const uint2* B2 = reinterpret_cast<const uint2*>(sm + B_OFF + s * 16384 + image * 8192);
        #pragma unroll
        for (int kg = 0; kg < 2; kg++) {
            uint2 bf[4];
            #pragma unroll
            for (int j = 0; j < 4; j++)
                bf[j] = B2[(kg * 16 + slab * 4 + j) * 32 + lane];
            #pragma unroll
            for (int m = 0; m < 4; m++) {
                uint4 a = A4[((m * 8 + ch) * 2 + kg) * 32 + lane];
                #pragma unroll
                for (int j = 0; j < 4; j++)
                    mma_f16(C[m][j], a.x, a.y, a.z, a.w, bf[j].x, bf[j].y);
            }
        }

        if (ch == 7) {
            // group epilogue: update running per-row min
            #pragma unroll
            for (int m = 0; m < 4; m++) {
                int r = m * 16 + g;
                float mn0 = 1e30f, mn1 = 1e30f;
                #pragma unroll
                for (int j = 0; j < 4; j++) {
                    int col = ctp * 256 + image * 128 + slab * 32 + j * 8 + 2 * tig;
                    float w0 = g_wsq[col], w1 = g_wsq[col + 1];
                    mn0 = fminf(mn0, fminf(fmaf(-2.f, C[m][j][0], w0), fmaf(-2.f, C[m][j][1], w1)));
                    mn1 = fminf(mn1, fminf(fmaf(-2.f, C[m][j][2], w0), fmaf(-2.f, C[m][j][3], w1)));
                }
                #pragma unroll
                for (int o = 1; o < 4; o <<= 1) {
                    mn0 = fminf(mn0, __shfl_xor_sync(0xffffffffu, mn0, o));
                    mn1 = fminf(mn1, __shfl_xor_sync(0xffffffffu, mn1, o));
                }
                if (tig == 0) {
                    sminA[r * 8 + wid] = fminf(sminA[r * 8 + wid], mn0);
                    sminA[(r + 8) * 8 + wid] = fminf(sminA[(r + 8) * 8 + wid], mn1);
                }
            }
            __syncthreads();
            if (tid < 64) {
                float v = sminA[tid * 8];
                #pragma unroll
                for (int t = 1; t < 8; t++) v = fminf(v, sminA[tid * 8 + t]);
                thrA[tid] = v + MARGIN;   // running threshold >= final threshold: never misses
            }
            __syncthreads();
            // push candidates from registers
            #pragma unroll
            for (int m = 0; m < 4; m++) {
                int r = m * 16 + g;
                float t0 = thrA[r], t1 = thrA[r + 8];
                #pragma unroll
                for (int j = 0; j < 4; j++) {
                    int col = ctp * 256 + image * 128 + slab * 32 + j * 8 + 2 * tig;
                    float w0 = g_wsq[col], w1 = g_wsq[col + 1];
                    float s00 = fmaf(-2.f, C[m][j][0], w0);
                    float s01 = fmaf(-2.f, C[m][j][1], w1);
                    float s10 = fmaf(-2.f, C[m][j][2], w0);
                    float s11 = fmaf(-2.f, C[m][j][3], w1);
                    if (s00 <= t0) { int p = atomicAdd(&cntA[r], 1);     if (p < CAND_MAX) candA[r * CAND_MAX + p] = col; }
                    if (s01 <= t0) { int p = atomicAdd(&cntA[r], 1);     if (p < CAND_MAX) candA[r * CAND_MAX + p] = col + 1; }
                    if (s10 <= t1) { int p = atomicAdd(&cntA[r + 8], 1); if (p < CAND_MAX) candA[(r + 8) * CAND_MAX + p] = col; }
                    if (s11 <= t1) { int p = atomicAdd(&cntA[r + 8], 1); if (p < CAND_MAX) candA[(r + 8) * CAND_MAX + p] = col + 1; }
                }
            }
        }
        __syncthreads();
        if (cc + 2 < 32) fillB(cc + 2);
    }

    // ---- phase 4: exact fp32 rescore of candidates (warp per row) ----
    for (int i = 0; i < 8; i++) {
        int r = wid * 8 + i;
        int cnt = cntA[r]; if (cnt > CAND_MAX) cnt = CAND_MAX;
        float sz = sumzA[r];
        float zr[8];
        #pragma unroll
        for (int j = 0; j < 8; j++)
            zr[j] = z[(size_t)(n0 + r) * D_DIM + lane + 32 * j];
        float best = 1e30f; int besti = K_CODES;
        for (int c = 0; c < cnt; c++) {
            int k = candA[r * CAND_MAX + c];
            const float* wr = g_wT + (size_t)k * D_DIM;
            float acc = 0.f;
            #pragma unroll
            for (int j = 0; j < 8; j++) acc = fmaf(zr[j], wr[lane + 32 * j], acc);
            #pragma unroll
            for (int o = 16; o > 0; o >>= 1)
                acc += __shfl_down_sync(0xffffffffu, acc, o);
            if (lane == 0) {
                float t = sz + g_wsq[k];
                float dist = fmaf(-2.f, acc, t);
                if (dist < best || (dist == best && k < besti)) { best = dist; besti = k; }
            }
        }
        if (lane == 0) cloA[r] = besti;
    }
    __syncthreads();

    // ---- phase 5a: gather + loss partial + stage output tile (overlays B/cand) ----
    float part = 0.f;
    float* qt = reinterpret_cast<float*>(sm + X_OFF);
    for (int i = 0; i < 8; i++) {
        int r = wid * 8 + i;
        int k = cloA[r];
        const float* wr = g_wT + (size_t)k * D_DIM;
        const float* zrow = z + (size_t)(n0 + r) * D_DIM;
        #pragma unroll
        for (int j = 0; j < 8; j++) {
            int d = lane + 32 * j;
            float q = wr[d], zv = zrow[d];
            float df = q - zv;
            part = fmaf(df, df, part);
            qt[r * QP + d] = zv + df;     // fl(z + fl(q - z)) matches ref ST
        }
    }

    redA[tid] = part;
    __syncthreads();
    #pragma unroll
    for (int st = 128; st > 0; st >>= 1) {
        if (tid < st) redA[tid] += redA[tid + st];
        __syncthreads();
    }
    if (tid == 0) g_partial[blockIdx.x] = redA[0];

    // ---- phase 5b: transposed write-out [B, D, H, W] ----
    int b = n0 >> 10, hw0 = n0 & 1023;
    #pragma unroll
    for (int i = 0; i < 16; i++) {
        int lin = i * 256 + tid;
        int d = lin >> 4;
        int hw4 = (lin & 15) * 4;
        float4 v;
        v.x = qt[(hw4 + 0) * QP + d];
        v.y = qt[(hw4 + 1) * QP + d];
        v.z = qt[(hw4 + 2) * QP + d];
        v.w = qt[(hw4 + 3) * QP + d];
        *reinterpret_cast<float4*>(out + (size_t)b * 262144 + (size_t)d * 1024 + hw0 + hw4) = v;
    }
}

// ---------------- kernel 4: finalize losses ----------------
__global__ void finalize_kernel(float* __restrict__ out, int out_size) {
    __shared__ double sdata[256];
    int tid = threadIdx.x;
    double s = (double)g_partial[tid] + (double)g_partial[tid + 256];
    sdata[tid] = s;
    __syncthreads();
    #pragma unroll
    for (int st = 128; st > 0; st >>= 1) {
        if (tid < st) sdata[tid] += sdata[tid + st];
        __syncthreads();
    }
    if (tid == 0) {
        float loss = (float)(sdata[0] / (double)OUT_ELEMS);
        out[out_size - 2] = loss;
        out[out_size - 1] = loss;
    }
}

// ---------------- launcher ----------------
extern "C" void kernel_launch(void* const* d_in, const int* in_sizes, int n_in,
                              void* d_out, int out_size) {
    (void)in_sizes; (void)n_in;
    const float* z = (const float*)d_in[0];
    const float* w = (const float*)d_in[1];
    float* out = (float*)d_out;

    static int inited = 0;
    if (!inited) {
        cudaFuncSetAttribute(fused_kernel, cudaFuncAttributeMaxDynamicSharedMemorySize, FUSED_SMEM);
        inited = 1;
    }

    wsq_kernel<<<K_CODES / 256, 256>>>(w);
    splitw_kernel<<<dim3(K_CODES / 32, D_DIM / 32), dim3(32, 8)>>>(w);
    fused_kernel<<<N_ROWS / 64, 256, FUSED_SMEM>>>(z, out);
    finalize_kernel<<<1, 256>>>(out, out_size);
}